// round 11
// baseline (speedup 1.0000x reference)
#include <cuda_runtime.h>
#include <cuda_bf16.h>
#include <math.h>
#include <stdint.h>

// ---------------- problem constants ----------------
#define V      200000
#define E      128
#define PAD    (V-1)
#define KNN_K  32
#define BQ     2048
#define BS     5
#define NN     128
#define KT     64
#define D      256
#define STEPS  4
#define H      512
#define NR     (2*BQ + 2*BS)   // 4106
#define MG     (2*NR)          // 8212

// ---------------- fp32 scratch ----------------
__device__ float g_gcn[(size_t)MG * E];
__device__ float g_X[(size_t)(BQ + BS) * D];
__device__ float g_Y[(size_t)(BQ + BS) * D];
__device__ float g_se[(size_t)(BQ + BS) * D];
__device__ float g_sg[D];
__device__ float g_bz[1024];                 // interleaved gate order: p = 4*e + gate
__device__ float g_zs[1024];
__device__ float g_zq[(size_t)BQ * 1024];    // interleaved gate order
__device__ float g_c[(size_t)BQ * D];
__device__ float g_h[(size_t)BQ * D];

// ---------------- bf16 hi/lo packed operands (K' = 3K) ----------------
__device__ __nv_bfloat16 g_Agcnp[(size_t)MG * 3 * D];
__device__ __nv_bfloat16 g_gWp  [(size_t)E * 3 * D];
__device__ __nv_bfloat16 g_Xp   [(size_t)(BQ + BS) * 3 * D];
__device__ __nv_bfloat16 g_w1p  [(size_t)H * 3 * D];
__device__ __nv_bfloat16 g_Tp   [(size_t)(BQ + BS) * 3 * H];
__device__ __nv_bfloat16 g_w2p  [(size_t)D * 3 * H];
__device__ __nv_bfloat16 g_Wihp [(size_t)1024 * 3 * D];   // row p = 4*e + gate
__device__ __nv_bfloat16 g_Whhp [(size_t)1024 * 3 * D];
__device__ __nv_bfloat16 g_sep  [(size_t)BQ * 3 * D];
__device__ __nv_bfloat16 g_hp   [(size_t)BQ * 3 * D];

__device__ __forceinline__ float sigm(float x) { return 1.f / (1.f + __expf(-x)); }

__device__ __forceinline__ void hilo(float x, __nv_bfloat16& hi, __nv_bfloat16& lo) {
    hi = __float2bfloat16(x);
    lo = __float2bfloat16(x - __bfloat162float(hi));
}

__device__ __forceinline__ float blk_reduce256(float v, float* sm) {
    int t = threadIdx.x;
#pragma unroll
    for (int o = 16; o; o >>= 1) v += __shfl_xor_sync(0xffffffffu, v, o);
    if ((t & 31) == 0) sm[t >> 5] = v;
    __syncthreads();
    if (t < 32) {
        float r = (t < 8) ? sm[t] : 0.f;
#pragma unroll
        for (int o = 4; o; o >>= 1) r += __shfl_xor_sync(0xffffffffu, r, o);
        if (t == 0) sm[0] = r;
    }
    __syncthreads();
    float r = sm[0];
    __syncthreads();
    return r;
}

// 128-thread block reduce (4 warps)
__device__ __forceinline__ float blk_reduce128(float v, float* sm) {
    int t = threadIdx.x;
#pragma unroll
    for (int o = 16; o; o >>= 1) v += __shfl_xor_sync(0xffffffffu, v, o);
    if ((t & 31) == 0) sm[t >> 5] = v;
    __syncthreads();
    float r = sm[0] + sm[1] + sm[2] + sm[3];
    __syncthreads();
    return r;
}

// ---------------- weight pack (B layout): fp32 -> [hi|hi|lo] ----------------
__global__ void packB_kernel(const float* __restrict__ in, __nv_bfloat16* __restrict__ out, int K)
{
    int r = blockIdx.x, t = threadIdx.x;
    const float* s = in + (size_t)r * K;
    __nv_bfloat16* d = out + (size_t)r * 3 * K;
    for (int k = t; k < K; k += blockDim.x) {
        __nv_bfloat16 hi, lo; hilo(s[k], hi, lo);
        d[k] = hi; d[K + k] = hi; d[2 * K + k] = lo;
    }
}

// ---------------- HMMA (mma.sync bf16) GEMM ----------------
// EPI: 0 = fp32 C; 1 = packed bf16 Cp (A layout, stride 3N);
//      2 = write fp32 C (=zq) AND fused LSTM step 1;
//      3 = fused LSTM step n (z = acc + bias(zs) + res(zq)), no C write.
__device__ __forceinline__ void mma16816(float* d, uint32_t a0, uint32_t a1, uint32_t a2, uint32_t a3,
                                         uint32_t b0, uint32_t b1)
{
    asm volatile(
        "mma.sync.aligned.m16n8k16.row.col.f32.bf16.bf16.f32 "
        "{%0,%1,%2,%3}, {%4,%5,%6,%7}, {%8,%9}, {%0,%1,%2,%3};"
        : "+f"(d[0]), "+f"(d[1]), "+f"(d[2]), "+f"(d[3])
        : "r"(a0), "r"(a1), "r"(a2), "r"(a3), "r"(b0), "r"(b1));
}

template<int ACT, int BM, int EPI>
__global__ __launch_bounds__(256)
void hmma_gemm(const __nv_bfloat16* __restrict__ Ap, const __nv_bfloat16* __restrict__ Bp,
               const float* __restrict__ bias, const float* __restrict__ res,
               float* __restrict__ C, __nv_bfloat16* __restrict__ Cp, int M, int N, int Kp)
{
    constexpr int BN = 64, LDS_ = 72;
    constexpr int WARPS_N = (BM == 128) ? 2 : 4;
    constexpr int WARPS_M = 8 / WARPS_N;
    constexpr int MI = BM / (WARPS_M * 16);
    constexpr int NI = BN / (WARPS_N * 8);
    constexpr int AIT = BM * 8 / 256;

    extern __shared__ __align__(16) char dsm[];
    __nv_bfloat16* Asm = (__nv_bfloat16*)dsm;
    __nv_bfloat16* Bsm = (__nv_bfloat16*)(dsm + 2 * BM * LDS_ * 2);

    const int tid = threadIdx.x, lane = tid & 31, wid = tid >> 5;
    const int wm = wid / WARPS_N, wn = wid % WARPS_N;
    const int grp = lane >> 2, thr = lane & 3;
    const int m0 = blockIdx.y * BM, n0 = blockIdx.x * BN;

    float acc[MI][NI][4];
#pragma unroll
    for (int i = 0; i < MI; i++)
#pragma unroll
        for (int j = 0; j < NI; j++)
#pragma unroll
            for (int q = 0; q < 4; q++) acc[i][j][q] = 0.f;

    uint4 ra[AIT], rb[2];
    const int nchunks = Kp >> 6;

#define LOAD_REGS(c)                                                            \
    {                                                                           \
        _Pragma("unroll")                                                       \
        for (int i = 0; i < AIT; i++) {                                         \
            int u = tid + i * 256; int row = u >> 3, seg = u & 7;               \
            int gr = m0 + row; if (gr >= M) gr = M - 1;                         \
            ra[i] = *(const uint4*)(Ap + (size_t)gr * Kp + (size_t)(c) * 64 + seg * 8); \
        }                                                                       \
        _Pragma("unroll")                                                       \
        for (int i = 0; i < 2; i++) {                                           \
            int u = tid + i * 256; int row = u >> 3, seg = u & 7;               \
            rb[i] = *(const uint4*)(Bp + (size_t)(n0 + row) * Kp + (size_t)(c) * 64 + seg * 8); \
        }                                                                       \
    }
#define STORE_REGS(buf)                                                         \
    {                                                                           \
        _Pragma("unroll")                                                       \
        for (int i = 0; i < AIT; i++) {                                         \
            int u = tid + i * 256; int row = u >> 3, seg = u & 7;               \
            *(uint4*)(Asm + (size_t)(buf) * BM * LDS_ + row * LDS_ + seg * 8) = ra[i]; \
        }                                                                       \
        _Pragma("unroll")                                                       \
        for (int i = 0; i < 2; i++) {                                           \
            int u = tid + i * 256; int row = u >> 3, seg = u & 7;               \
            *(uint4*)(Bsm + (size_t)(buf) * BN * LDS_ + row * LDS_ + seg * 8) = rb[i]; \
        }                                                                       \
    }
#define COMPUTE(buf)                                                            \
    {                                                                           \
        const __nv_bfloat16* A_ = Asm + (size_t)(buf) * BM * LDS_;              \
        const __nv_bfloat16* B_ = Bsm + (size_t)(buf) * BN * LDS_;              \
        _Pragma("unroll")                                                       \
        for (int kk = 0; kk < 4; kk++) {                                        \
            int k0 = kk * 16;                                                   \
            uint32_t af[MI][4];                                                 \
            _Pragma("unroll")                                                   \
            for (int mi = 0; mi < MI; mi++) {                                   \
                int r = wm * (MI * 16) + mi * 16 + grp;                         \
                af[mi][0] = *(const uint32_t*)(A_ + r * LDS_ + k0 + thr * 2);   \
                af[mi][1] = *(const uint32_t*)(A_ + (r + 8) * LDS_ + k0 + thr * 2); \
                af[mi][2] = *(const uint32_t*)(A_ + r * LDS_ + k0 + 8 + thr * 2);   \
                af[mi][3] = *(const uint32_t*)(A_ + (r + 8) * LDS_ + k0 + 8 + thr * 2); \
            }                                                                   \
            _Pragma("unroll")                                                   \
            for (int ni = 0; ni < NI; ni++) {                                   \
                int cN = wn * (NI * 8) + ni * 8 + grp;                          \
                uint32_t b0 = *(const uint32_t*)(B_ + cN * LDS_ + k0 + thr * 2);    \
                uint32_t b1 = *(const uint32_t*)(B_ + cN * LDS_ + k0 + 8 + thr * 2);\
                _Pragma("unroll")                                               \
                for (int mi = 0; mi < MI; mi++)                                 \
                    mma16816(acc[mi][ni], af[mi][0], af[mi][1], af[mi][2], af[mi][3], b0, b1); \
            }                                                                   \
        }                                                                       \
    }

    LOAD_REGS(0);
    STORE_REGS(0);
    __syncthreads();

    int cur = 0;
    for (int c = 1; c < nchunks; c++) {
        LOAD_REGS(c);
        COMPUTE(cur);
        STORE_REGS(cur ^ 1);
        __syncthreads();
        cur ^= 1;
    }
    COMPUTE(cur);

    if (EPI <= 1) {
#pragma unroll
        for (int mi = 0; mi < MI; mi++) {
#pragma unroll
            for (int ni = 0; ni < NI; ni++) {
                int col = n0 + wn * (NI * 8) + ni * 8 + thr * 2;
                float2 bb = *(const float2*)(bias + col);
#pragma unroll
                for (int half = 0; half < 2; half++) {
                    int row = m0 + wm * (MI * 16) + mi * 16 + grp + half * 8;
                    if (row >= M) continue;
                    float v0 = acc[mi][ni][half * 2 + 0] + bb.x;
                    float v1 = acc[mi][ni][half * 2 + 1] + bb.y;
                    if (res) {
                        float2 rr = *(const float2*)(res + (size_t)row * N + col);
                        v0 += rr.x; v1 += rr.y;
                    }
                    if (ACT == 1) { v0 = fmaxf(v0, 0.f); v1 = fmaxf(v1, 0.f); }
                    if (ACT == 2) { v0 = tanhf(v0); v1 = tanhf(v1); }
                    if (EPI == 0) {
                        float2 o; o.x = v0; o.y = v1;
                        *(float2*)(C + (size_t)row * N + col) = o;
                    } else {
                        __nv_bfloat16 h0, l0, h1, l1;
                        hilo(v0, h0, l0); hilo(v1, h1, l1);
                        __nv_bfloat16* dst = Cp + (size_t)row * 3 * N;
                        __nv_bfloat162 hh; hh.x = h0; hh.y = h1;
                        __nv_bfloat162 ll; ll.x = l0; ll.y = l1;
                        *(__nv_bfloat162*)(dst + col)         = hh;
                        *(__nv_bfloat162*)(dst + N + col)     = ll;
                        *(__nv_bfloat162*)(dst + 2 * N + col) = hh;
                    }
                }
            }
        }
    } else {
        // fused LSTM epilogue. cols interleaved: col = 4*e + gate.
        // lane pair (thr even, thr odd) owns gates (i,f) and (g,o) of same e.
#pragma unroll
        for (int mi = 0; mi < MI; mi++) {
#pragma unroll
            for (int ni = 0; ni < NI; ni++) {
                int col = n0 + wn * (NI * 8) + ni * 8 + thr * 2;
                float2 bb = *(const float2*)(bias + col);   // bz (EPI2) or zs (EPI3)
#pragma unroll
                for (int half = 0; half < 2; half++) {
                    int row = m0 + wm * (MI * 16) + mi * 16 + grp + half * 8;
                    float v0 = acc[mi][ni][half * 2 + 0] + bb.x;
                    float v1 = acc[mi][ni][half * 2 + 1] + bb.y;
                    if (EPI == 3) {
                        float2 rr = *(const float2*)(res + (size_t)row * N + col);
                        v0 += rr.x; v1 += rr.y;
                    }
                    if (EPI == 2) {
                        float2 o; o.x = v0; o.y = v1;
                        *(float2*)(C + (size_t)row * N + col) = o;   // zq for later steps
                    }
                    float p0 = __shfl_xor_sync(0xffffffffu, v0, 1);
                    float p1 = __shfl_xor_sync(0xffffffffu, v1, 1);
                    if ((thr & 1) == 0) {
                        int e = col >> 2;
                        float zi = v0, zf = v1, zg = p0, zo = p1;
                        size_t idx = (size_t)row * D + e;
                        float c;
                        if (EPI == 2) c = sigm(zi) * tanhf(zg);
                        else          c = sigm(zf) * g_c[idx] + sigm(zi) * tanhf(zg);
                        g_c[idx] = c;
                        float hv = g_se[idx] + sigm(zo) * tanhf(c);
                        g_h[idx] = hv;
                        __nv_bfloat16 hi, lo; hilo(hv, hi, lo);
                        size_t b = (size_t)row * 3 * D;
                        g_hp[b + e] = hi; g_hp[b + D + e] = lo; g_hp[b + 2*D + e] = hi;
                    }
                }
            }
        }
    }
#undef LOAD_REGS
#undef STORE_REGS
#undef COMPUTE
}

// ---------------- K1: neighbor encoder gather/top-k/mean -> packed A rows ----------------
__global__ void nbr_kernel(const float* __restrict__ emb,
                           const int* __restrict__ query,
                           const int* __restrict__ support,
                           const int* __restrict__ qlc,
                           const int* __restrict__ qrc,
                           const int* __restrict__ slc,
                           const int* __restrict__ src,
                           const int* __restrict__ knn)
{
    int r = blockIdx.x;
    int tid = threadIdx.x, lane = tid & 31, warp = tid >> 5;

    const int* conn; int eid;
    if (r < BQ)               { eid = query[2*r];                 conn = qlc + (size_t)r*NN*2; }
    else if (r < 2*BQ)        { int b=r-BQ;   eid = query[2*b+1]; conn = qrc + (size_t)b*NN*2; }
    else if (r < 2*BQ+BS)     { int b=r-2*BQ; eid = support[2*b]; conn = slc + (size_t)b*NN*2; }
    else                      { int b=r-2*BQ-BS; eid = support[2*b+1]; conn = src + (size_t)b*NN*2; }
    if (eid < 0 || eid >= V) eid = PAD;

    __shared__ __align__(16) float cs[E];
    __shared__ float sims[NN];
    __shared__ float sumE[E], sumR[E], sumK[E];
    __shared__ int idsR[NN], idsE[NN], kid[KT], sel[KNN_K];
    __shared__ int selcnt;
    __shared__ float s_cn;

    if (tid < E) { cs[tid] = emb[(size_t)eid*E + tid]; sumE[tid]=0.f; sumR[tid]=0.f; sumK[tid]=0.f; }
    if (tid < NN) {
        int a = conn[2*tid], b = conn[2*tid+1];
        idsR[tid] = min(max(a,0), V-1);
        idsE[tid] = min(max(b,0), V-1);
    }
    if (tid < KT) { int kk = knn[(size_t)eid*KT + tid]; if (kk < 0 || kk >= V) kk = PAD; kid[tid] = kk; }
    if (tid == 0) selcnt = 0;
    __syncthreads();

    if (warp == 0) {
        float4 c = ((const float4*)cs)[lane];
        float s = c.x*c.x + c.y*c.y + c.z*c.z + c.w*c.w;
#pragma unroll
        for (int o = 16; o; o >>= 1) s += __shfl_xor_sync(0xffffffffu, s, o);
        if (lane == 0) s_cn = fmaxf(sqrtf(s), 1e-8f);
    }
    __syncthreads();
    float cn = s_cn;
    float4 c4 = ((const float4*)cs)[lane];

    // sims vs ent neighbors — 2-row unroll for MLP
    for (int n = warp; n < NN; n += 16) {
        int n2 = n + 8;
        float4 va = ((const float4*)(emb + (size_t)idsE[n]*E))[lane];
        float4 vb = ((const float4*)(emb + (size_t)idsE[n2]*E))[lane];
        float dda = va.x*c4.x + va.y*c4.y + va.z*c4.z + va.w*c4.w;
        float qqa = va.x*va.x + va.y*va.y + va.z*va.z + va.w*va.w;
        float ddb = vb.x*c4.x + vb.y*c4.y + vb.z*c4.z + vb.w*c4.w;
        float qqb = vb.x*vb.x + vb.y*vb.y + vb.z*vb.z + vb.w*vb.w;
#pragma unroll
        for (int o = 16; o; o >>= 1) {
            dda += __shfl_xor_sync(0xffffffffu, dda, o);
            qqa += __shfl_xor_sync(0xffffffffu, qqa, o);
            ddb += __shfl_xor_sync(0xffffffffu, ddb, o);
            qqb += __shfl_xor_sync(0xffffffffu, qqb, o);
        }
        if (lane == 0) {
            sims[n]  = dda / (cn * fmaxf(sqrtf(qqa), 1e-8f));
            sims[n2] = ddb / (cn * fmaxf(sqrtf(qqb), 1e-8f));
        }
    }
    __syncthreads();

    if (tid < NN) {
        float sn = sims[tid]; int cnt = 0;
#pragma unroll 4
        for (int m = 0; m < NN; m++) {
            float sm = sims[m];
            cnt += (sm > sn) || (sm == sn && m < tid);
        }
        if (cnt < KNN_K) { int p = atomicAdd(&selcnt, 1); sel[p] = tid; }
    }
    __syncthreads();

    {
        float4 aE = make_float4(0,0,0,0), aR = make_float4(0,0,0,0);
        for (int p = warp; p < KNN_K; p += 16) {
            int n1 = sel[p], n2 = sel[p + 8];
            float4 v1 = ((const float4*)(emb + (size_t)idsE[n1]*E))[lane];
            float4 w1 = ((const float4*)(emb + (size_t)idsR[n1]*E))[lane];
            float4 v2 = ((const float4*)(emb + (size_t)idsE[n2]*E))[lane];
            float4 w2 = ((const float4*)(emb + (size_t)idsR[n2]*E))[lane];
            aE.x += v1.x + v2.x; aE.y += v1.y + v2.y; aE.z += v1.z + v2.z; aE.w += v1.w + v2.w;
            aR.x += w1.x + w2.x; aR.y += w1.y + w2.y; aR.z += w1.z + w2.z; aR.w += w1.w + w2.w;
        }
        atomicAdd(&sumE[lane*4+0], aE.x); atomicAdd(&sumE[lane*4+1], aE.y);
        atomicAdd(&sumE[lane*4+2], aE.z); atomicAdd(&sumE[lane*4+3], aE.w);
        atomicAdd(&sumR[lane*4+0], aR.x); atomicAdd(&sumR[lane*4+1], aR.y);
        atomicAdd(&sumR[lane*4+2], aR.z); atomicAdd(&sumR[lane*4+3], aR.w);
    }
    __syncthreads();
    if (tid == 0) selcnt = 0;

    // knn branch sims — 2-row unroll
    for (int n = warp; n < KT; n += 16) {
        int n2 = n + 8;
        float4 va = ((const float4*)(emb + (size_t)kid[n]*E))[lane];
        float4 vb = ((const float4*)(emb + (size_t)kid[n2]*E))[lane];
        float dda = va.x*c4.x + va.y*c4.y + va.z*c4.z + va.w*c4.w;
        float qqa = va.x*va.x + va.y*va.y + va.z*va.z + va.w*va.w;
        float ddb = vb.x*c4.x + vb.y*c4.y + vb.z*c4.z + vb.w*c4.w;
        float qqb = vb.x*vb.x + vb.y*vb.y + vb.z*vb.z + vb.w*vb.w;
#pragma unroll
        for (int o = 16; o; o >>= 1) {
            dda += __shfl_xor_sync(0xffffffffu, dda, o);
            qqa += __shfl_xor_sync(0xffffffffu, qqa, o);
            ddb += __shfl_xor_sync(0xffffffffu, ddb, o);
            qqb += __shfl_xor_sync(0xffffffffu, qqb, o);
        }
        if (lane == 0) {
            sims[n]  = dda / (cn * fmaxf(sqrtf(qqa), 1e-8f));
            sims[n2] = ddb / (cn * fmaxf(sqrtf(qqb), 1e-8f));
        }
    }
    __syncthreads();

    if (tid < KT) {
        float sn = sims[tid]; int cnt = 0;
#pragma unroll 4
        for (int m = 0; m < KT; m++) {
            float sm = sims[m];
            cnt += (sm > sn) || (sm == sn && m < tid);
        }
        if (cnt < KNN_K) { int p = atomicAdd(&selcnt, 1); sel[p] = tid; }
    }
    __syncthreads();

    {
        float4 aK = make_float4(0,0,0,0);
        for (int p = warp; p < KNN_K; p += 16) {
            int n1 = sel[p], n2 = sel[p + 8];
            float4 v1 = ((const float4*)(emb + (size_t)kid[n1]*E))[lane];
            float4 v2 = ((const float4*)(emb + (size_t)kid[n2]*E))[lane];
            aK.x += v1.x + v2.x; aK.y += v1.y + v2.y; aK.z += v1.z + v2.z; aK.w += v1.w + v2.w;
        }
        atomicAdd(&sumK[lane*4+0], aK.x); atomicAdd(&sumK[lane*4+1], aK.y);
        atomicAdd(&sumK[lane*4+2], aK.z); atomicAdd(&sumK[lane*4+3], aK.w);
    }
    __syncthreads();

    if (tid < E) {
        const float inv = 1.f / (float)KNN_K;
        float vr = sumR[tid] * inv, ve = sumE[tid] * inv, vk = sumK[tid] * inv;
        __nv_bfloat16 hr, lr, he, le, hk, lk;
        hilo(vr, hr, lr); hilo(ve, he, le); hilo(vk, hk, lk);
        const __nv_bfloat16 z0 = __float2bfloat16(0.f);
        size_t b1 = (size_t)r * 3 * D;
        g_Agcnp[b1 + tid]           = hr;  g_Agcnp[b1 + E + tid]           = he;
        g_Agcnp[b1 + D + tid]       = lr;  g_Agcnp[b1 + D + E + tid]       = le;
        g_Agcnp[b1 + 2*D + tid]     = hr;  g_Agcnp[b1 + 2*D + E + tid]     = he;
        size_t b2 = (size_t)(NR + r) * 3 * D;
        g_Agcnp[b2 + tid]           = z0;  g_Agcnp[b2 + E + tid]           = hk;
        g_Agcnp[b2 + D + tid]       = z0;  g_Agcnp[b2 + D + E + tid]       = lk;
        g_Agcnp[b2 + 2*D + tid]     = z0;  g_Agcnp[b2 + 2*D + E + tid]     = hk;
    }
}

// ---------------- K3: sigmoid gate + concat -> X fp32 + Xp packed (128 threads) ----------------
__global__ void gate_kernel(const float* __restrict__ gate_W, const float* __restrict__ gate_b)
{
    __shared__ float sm[4];
    int r = blockIdx.x, t = threadIdx.x;   // 128 threads, all active
    float s = g_gcn[(size_t)r * E + t];
    float k = g_gcn[(size_t)(NR + r) * E + t];
    float part = s * gate_W[t] + k * gate_W[E + t];
    float ain = blk_reduce128(part, sm);
    float a = sigm(ain + gate_b[0]);
    float f = (1.f - a) * s + a * k;
    int row, col;
    if (r < BQ)            { row = r;              col = t; }
    else if (r < 2*BQ)     { row = r - BQ;         col = E + t; }
    else if (r < 2*BQ+BS)  { row = BQ + r - 2*BQ;  col = t; }
    else                   { row = BQ + r - 2*BQ - BS; col = E + t; }
    g_X[(size_t)row * D + col] = f;
    __nv_bfloat16 hi, lo; hilo(f, hi, lo);
    size_t b = (size_t)row * 3 * D;
    g_Xp[b + col] = hi; g_Xp[b + D + col] = lo; g_Xp[b + 2*D + col] = hi;
}

// ---------------- K6: layernorm -> se fp32 + sep packed (query rows) ----------------
__global__ void ln_kernel(const float* __restrict__ ln_g, const float* __restrict__ ln_b)
{
    __shared__ float sm[8];
    int r = blockIdx.x, t = threadIdx.x;
    float x = g_Y[(size_t)r * D + t];
    float mu = blk_reduce256(x, sm) * (1.f / D);
    float d = x - mu;
    float var = blk_reduce256(d * d, sm) * (1.f / D);
    float v = d * rsqrtf(var + 1e-5f) * ln_g[t] + ln_b[t];
    g_se[(size_t)r * D + t] = v;
    if (r < BQ) {
        __nv_bfloat16 hi, lo; hilo(v, hi, lo);
        size_t b = (size_t)r * 3 * D;
        g_sep[b + t] = hi; g_sep[b + D + t] = lo; g_sep[b + 2*D + t] = hi;
    }
}

// ---------------- K7: support_g ----------------
__global__ void sg_kernel()
{
    int t = threadIdx.x;
    float s = 0.f;
#pragma unroll
    for (int i = 0; i < BS; i++) s += g_se[(size_t)(BQ + i) * D + t];
    g_sg[t] = s * (1.f / BS);
}

// ---------------- K8: pack LSTM weights (interleaved gate rows) + zs, bz ----------------
__global__ void pack_kernel(const float* __restrict__ W_ih, const float* __restrict__ W_hh,
                            const float* __restrict__ b_ih, const float* __restrict__ b_hh)
{
    __shared__ float sm[8];
    int p = blockIdx.x;          // p = 4*e + gate
    int t = threadIdx.x;
    int gate = p & 3, e = p >> 2;
    int orig = gate * 512 + e;   // i:0.. f:512.. g:1024.. o:1536..
    float wih = W_ih[(size_t)orig * D + t];
    float whh = W_hh[(size_t)orig * H + t];
    {
        __nv_bfloat16 hi, lo; hilo(wih, hi, lo);
        size_t b = (size_t)p * 3 * D;
        g_Wihp[b + t] = hi; g_Wihp[b + D + t] = hi; g_Wihp[b + 2*D + t] = lo;
    }
    {
        __nv_bfloat16 hi, lo; hilo(whh, hi, lo);
        size_t b = (size_t)p * 3 * D;
        g_Whhp[b + t] = hi; g_Whhp[b + D + t] = hi; g_Whhp[b + 2*D + t] = lo;
    }
    float part = W_hh[(size_t)orig * H + D + t] * g_sg[t];
    float zsv = blk_reduce256(part, sm);
    if (t == 0) {
        g_zs[p] = zsv;
        g_bz[p] = b_ih[orig] + b_hh[orig];
    }
}

// ---------------- K13: cosine output ----------------
__global__ void final_kernel(float* __restrict__ out)
{
    __shared__ float sm[8];
    int b = blockIdx.x, t = threadIdx.x;
    float hv = g_h[(size_t)b * D + t];
    float sv = g_sg[t];
    float dot = blk_reduce256(hv * sv, sm);
    float hh  = blk_reduce256(hv * hv, sm);
    float ss  = blk_reduce256(sv * sv, sm);
    if (t == 0)
        out[b] = dot / (fmaxf(sqrtf(hh), 1e-12f) * fmaxf(sqrtf(ss), 1e-12f));
}

// ---------------- launch ----------------
#define SMEM_BM128 ((2 * 128 * 72 + 2 * 64 * 72) * 2)   // 55296
#define SMEM_BM64  ((2 * 64 * 72 + 2 * 64 * 72) * 2)    // 36864
#define SMEM_BM32  ((2 * 32 * 72 + 2 * 64 * 72) * 2)    // 27648

extern "C" void kernel_launch(void* const* d_in, const int* in_sizes, int n_in,
                              void* d_out, int out_size)
{
    const float* emb    = (const float*)d_in[0];
    const float* gcn_W  = (const float*)d_in[1];
    const float* gcn_wb = (const float*)d_in[2];
    const float* gate_W = (const float*)d_in[3];
    const float* gate_b = (const float*)d_in[4];
    const float* se_w1  = (const float*)d_in[5];
    const float* se_b1  = (const float*)d_in[6];
    const float* se_w2  = (const float*)d_in[7];
    const float* se_b2  = (const float*)d_in[8];
    const float* ln_g   = (const float*)d_in[9];
    const float* ln_b   = (const float*)d_in[10];
    const float* W_ih   = (const float*)d_in[11];
    const float* W_hh   = (const float*)d_in[12];
    const float* b_ih   = (const float*)d_in[13];
    const float* b_hh   = (const float*)d_in[14];
    const int*   query  = (const int*)d_in[15];
    const int*   support= (const int*)d_in[16];
    const int*   qlc    = (const int*)d_in[17];
    const int*   qrc    = (const int*)d_in[19];
    const int*   slc    = (const int*)d_in[21];
    const int*   src    = (const int*)d_in[23];
    const int*   knn    = (const int*)d_in[25];
    float* out = (float*)d_out;

    float *gcn, *X, *Y, *se, *bz, *zs, *zq;
    __nv_bfloat16 *Agcnp, *gWp, *Xp, *w1p, *Tp, *w2p, *Wihp, *Whhp, *sep, *hp;
    cudaGetSymbolAddress((void**)&gcn,  g_gcn);
    cudaGetSymbolAddress((void**)&X,    g_X);
    cudaGetSymbolAddress((void**)&Y,    g_Y);
    cudaGetSymbolAddress((void**)&se,   g_se);
    cudaGetSymbolAddress((void**)&bz,   g_bz);
    cudaGetSymbolAddress((void**)&zs,   g_zs);
    cudaGetSymbolAddress((void**)&zq,   g_zq);
    cudaGetSymbolAddress((void**)&Agcnp, g_Agcnp);
    cudaGetSymbolAddress((void**)&gWp,   g_gWp);
    cudaGetSymbolAddress((void**)&Xp,    g_Xp);
    cudaGetSymbolAddress((void**)&w1p,   g_w1p);
    cudaGetSymbolAddress((void**)&Tp,    g_Tp);
    cudaGetSymbolAddress((void**)&w2p,   g_w2p);
    cudaGetSymbolAddress((void**)&Wihp,  g_Wihp);
    cudaGetSymbolAddress((void**)&Whhp,  g_Whhp);
    cudaGetSymbolAddress((void**)&sep,   g_sep);
    cudaGetSymbolAddress((void**)&hp,    g_hp);

    cudaFuncSetAttribute(hmma_gemm<0,128,2>, cudaFuncAttributeMaxDynamicSharedMemorySize, SMEM_BM128);
    cudaFuncSetAttribute(hmma_gemm<0,128,3>, cudaFuncAttributeMaxDynamicSharedMemorySize, SMEM_BM128);

    // K1: neighbor gather / top-k / means -> packed A rows
    nbr_kernel<<<NR, 256>>>(emb, query, support, qlc, qrc, slc, src, knn);

    // K2: gcn GEMM [8212,256]@[128,256]^T -> tanh, fp32 out
    packB_kernel<<<E, 256>>>(gcn_W, gWp, D);
    hmma_gemm<2,64,0><<<dim3(E/64, (MG+63)/64), 256, SMEM_BM64>>>(Agcnp, gWp, gcn_wb, nullptr, gcn, nullptr, MG, E, 3*D);

    // K3: gate + concat
    gate_kernel<<<NR, 128>>>(gate_W, gate_b);

    // K4: se layer 1 -> relu, packed out Tp
    packB_kernel<<<H, 256>>>(se_w1, w1p, D);
    hmma_gemm<1,64,1><<<dim3(H/64, (BQ+BS+63)/64), 256, SMEM_BM64>>>(Xp, w1p, se_b1, nullptr, nullptr, Tp, BQ+BS, H, 3*D);

    // K5: se layer 2 + b2 + X -> Y fp32  (BM=32: 260 CTAs)
    packB_kernel<<<D, 256>>>(se_w2, w2p, H);
    hmma_gemm<0,32,0><<<dim3(D/64, (BQ+BS+31)/32), 256, SMEM_BM32>>>(Tp, w2p, se_b2, X, Y, nullptr, BQ+BS, D, 3*H);

    // K6/K7/K8
    ln_kernel<<<BQ + BS, 256>>>(ln_g, ln_b);
    sg_kernel<<<1, 256>>>();
    pack_kernel<<<1024, 256>>>(W_ih, W_hh, b_ih, b_hh);

    // K9: zq = query_g @ Wih^T + bz, fused LSTM step 1
    hmma_gemm<0,128,2><<<dim3(1024/64, BQ/128), 256, SMEM_BM128>>>(sep, Wihp, bz, nullptr, zq, nullptr, BQ, 1024, 3*D);

    // steps 2..4: fused z-GEMM + LSTM elementwise
    for (int s = 1; s < STEPS; s++) {
        hmma_gemm<0,128,3><<<dim3(1024/64, BQ/128), 256, SMEM_BM128>>>(hp, Whhp, zs, zq, nullptr, nullptr, BQ, 1024, 3*D);
    }

    final_kernel<<<BQ, 256>>>(out);
}